// round 1
// baseline (speedup 1.0000x reference)
#include <cuda_runtime.h>
#include <math.h>

// Problem constants
#define NB   16
#define NT   512
#define NC   128
#define NDM  512
#define NL   3
#define NP   64
#define NKS  25
#define NM   (NB*NC)       // 2048 rows
#define NH   (2*NDM)       // 1024 FFN hidden

// Scratch (device globals: no allocation allowed)
__device__ float g_R [NM*NT];
__device__ float g_X [NM*NDM];
__device__ float g_B1[NM*NH];
__device__ float g_B2[NM*NDM];
__device__ float g_B3[NM*NDM];
__device__ float g_S [NM];

// -------------------------------------------------------------------------
// 1) trend conv (replicate pad, ks=25) + residual, with transpose to (B,C,T)
// grid (B, T/64, C/32), block 256
__global__ void conv_residual_kernel(const float* __restrict__ inp,
                                     const float* __restrict__ w,
                                     const float* __restrict__ ldb,
                                     float* __restrict__ R) {
    __shared__ float s[88][33];
    __shared__ float wk[NKS];
    int b = blockIdx.x, t0 = blockIdx.y * 64, c0 = blockIdx.z * 32;
    int tid = threadIdx.x;
    if (tid < NKS) wk[tid] = w[tid];
    for (int idx = tid; idx < 88 * 32; idx += 256) {
        int r = idx >> 5, c = idx & 31;
        int tg = t0 + r - 12;
        tg = min(max(tg, 0), NT - 1);
        s[r][c] = inp[((size_t)b * NT + tg) * NC + c0 + c];
    }
    __syncthreads();
    float lb = ldb[0];
    int lane = tid & 31, wy = tid >> 5;
    for (int half = 0; half < 2; ++half) {
        int ti = half * 32 + lane;
        for (int cg = 0; cg < 4; ++cg) {
            int ci = cg * 8 + wy;
            float acc = 0.f;
            #pragma unroll
            for (int k = 0; k < NKS; ++k) acc = fmaf(wk[k], s[ti + k][ci], acc);
            float v = s[ti + 12][ci] - (acc + lb);
            R[((size_t)b * NC + c0 + ci) * NT + t0 + ti] = v;
        }
    }
}

// -------------------------------------------------------------------------
// 2) generic fp32 GEMM: C[m,n] = sum_k A[m,k]*W(k,n) + epilogue
// LAY_NT: W is (N,K) row-major (y = x @ W.T). LAY_NN: W is (K,N) row-major.
// BM=128, BN=64, BK=16, 128 threads, 8x8 micro-tile.
enum { LAY_NT = 0, LAY_NN = 1 };
enum { EPI_NONE = 0, EPI_BIAS, EPI_BIAS_WPOS, EPI_BIAS_GELU, EPI_BIAS_RES, EPI_BIAS_RES_BN };

#define GBM 128
#define GBN 64
#define GBK 16

template<int LAYOUT, int EPI>
__global__ __launch_bounds__(128)
void gemm_kernel(const float* __restrict__ A, const float* __restrict__ W,
                 const float* __restrict__ bias, const float* __restrict__ extra,
                 const float* __restrict__ bng, const float* __restrict__ bnb,
                 float* __restrict__ C, int M, int N, int K) {
    __shared__ float As[GBK][GBM + 4];
    __shared__ float Bs[GBK][GBN + 4];
    int m0 = blockIdx.y * GBM, n0 = blockIdx.x * GBN;
    int tid = threadIdx.x;
    int tidy = tid >> 3, tidx = tid & 7;

    float acc[8][8];
    #pragma unroll
    for (int i = 0; i < 8; i++)
        #pragma unroll
        for (int j = 0; j < 8; j++) acc[i][j] = 0.f;

    for (int k0 = 0; k0 < K; k0 += GBK) {
        #pragma unroll
        for (int it = 0; it < 4; ++it) {          // A tile: 128x16 = 512 float4
            int f = tid + it * 128;
            int mo = f >> 2, k4 = (f & 3) * 4;
            float4 v = *(const float4*)(A + (size_t)(m0 + mo) * K + k0 + k4);
            As[k4 + 0][mo] = v.x; As[k4 + 1][mo] = v.y;
            As[k4 + 2][mo] = v.z; As[k4 + 3][mo] = v.w;
        }
        #pragma unroll
        for (int it = 0; it < 2; ++it) {          // B tile: 64x16 = 256 float4
            int f = tid + it * 128;
            if (LAYOUT == LAY_NT) {
                int no = f >> 2, k4 = (f & 3) * 4;
                float4 v = *(const float4*)(W + (size_t)(n0 + no) * K + k0 + k4);
                Bs[k4 + 0][no] = v.x; Bs[k4 + 1][no] = v.y;
                Bs[k4 + 2][no] = v.z; Bs[k4 + 3][no] = v.w;
            } else {
                int ko = f >> 4, n4 = (f & 15) * 4;
                float4 v = *(const float4*)(W + (size_t)(k0 + ko) * N + n0 + n4);
                *(float4*)&Bs[ko][n4] = v;
            }
        }
        __syncthreads();
        #pragma unroll
        for (int kk = 0; kk < GBK; kk++) {
            float a[8], bb[8];
            *(float4*)&a[0]  = *(float4*)&As[kk][tidy * 8];
            *(float4*)&a[4]  = *(float4*)&As[kk][tidy * 8 + 4];
            *(float4*)&bb[0] = *(float4*)&Bs[kk][tidx * 8];
            *(float4*)&bb[4] = *(float4*)&Bs[kk][tidx * 8 + 4];
            #pragma unroll
            for (int i = 0; i < 8; i++)
                #pragma unroll
                for (int j = 0; j < 8; j++) acc[i][j] = fmaf(a[i], bb[j], acc[i][j]);
        }
        __syncthreads();
    }

    const float invs = 0.9999950000374997f;   // 1/sqrt(1+1e-5) for eval-mode BN
    #pragma unroll
    for (int i = 0; i < 8; i++) {
        int m = m0 + tidy * 8 + i;
        float bsc = 1.f, bof = 0.f;
        if (EPI == EPI_BIAS_RES_BN) { bsc = bng[m & (NC - 1)] * invs; bof = bnb[m & (NC - 1)]; }
        #pragma unroll
        for (int j = 0; j < 8; j += 4) {
            int n = n0 + tidx * 8 + j;
            float4 v; float* pv = (float*)&v;
            #pragma unroll
            for (int q = 0; q < 4; q++) {
                float x = acc[i][j + q];
                if (EPI != EPI_NONE) x += bias[n + q];
                if (EPI == EPI_BIAS_WPOS) x += extra[(size_t)(m & (NC - 1)) * N + n + q];
                if (EPI == EPI_BIAS_RES || EPI == EPI_BIAS_RES_BN) x += extra[(size_t)m * N + n + q];
                if (EPI == EPI_BIAS_GELU) x = 0.5f * x * (1.f + erff(x * 0.7071067811865475f));
                if (EPI == EPI_BIAS_RES_BN) x = x * bsc + bof;
                pv[q] = x;
            }
            *(float4*)(C + (size_t)m * N + n) = v;
        }
    }
}

// -------------------------------------------------------------------------
// 3) row sums (varcor rank-1 logits). one warp per row.
__global__ void rowsum_kernel(const float* __restrict__ X, float* __restrict__ S) {
    int row = blockIdx.x * 8 + (threadIdx.x >> 5);
    int lane = threadIdx.x & 31;
    const float* xr = X + (size_t)row * NDM;
    float s = 0.f;
    for (int i = lane; i < NDM; i += 32) s += xr[i];
    #pragma unroll
    for (int o = 16; o; o >>= 1) s += __shfl_xor_sync(0xffffffffu, s, o);
    if (!lane) S[row] = s;
}

// -------------------------------------------------------------------------
// 4) varcor mix + residual + BN.  grid (B, DM/64), 256 threads (2 per d-row).
// corr[b,d,e] = S_d*S_e/DM ; softmax_e( corr * DM^-0.5 ) ; y = corr@x ; (+x)*bn
__global__ void varcor_kernel(const float* __restrict__ X, const float* __restrict__ S,
                              const float* __restrict__ bng, const float* __restrict__ bnb,
                              float* __restrict__ Out) {
    __shared__ float xs[NC][64];
    __shared__ float ss[NC];
    int b = blockIdx.x, j0 = blockIdx.y * 64;
    int tid = threadIdx.x;
    if (tid < NC) ss[tid] = S[b * NC + tid];
    const float* xb = X + (size_t)b * NC * NDM;
    for (int f = tid; f < NC * 16; f += 256) {
        int e = f >> 4, q = f & 15;
        *(float4*)&xs[e][q * 4] = ((const float4*)(xb + (size_t)e * NDM + j0))[q];
    }
    __syncthreads();

    int d = tid >> 1, half = tid & 1;
    const float VS = 8.6316746e-05f;            // 1/(512*sqrt(512))
    float sd = ss[d];
    float mx = -1e30f;
    for (int e = 0; e < NC; e++) mx = fmaxf(mx, sd * ss[e]);
    float sum = 0.f;
    for (int e = 0; e < NC; e++) sum += __expf((sd * ss[e] - mx) * VS);
    float rs = 1.f / sum;

    float4 acc[8];
    #pragma unroll
    for (int t = 0; t < 8; t++) acc[t] = make_float4(0.f, 0.f, 0.f, 0.f);
    int jb = half * 32;
    for (int e = 0; e < NC; e++) {
        float w = __expf((sd * ss[e] - mx) * VS) * rs;
        #pragma unroll
        for (int t = 0; t < 8; t++) {
            float4 xv = *(float4*)&xs[e][jb + t * 4];
            acc[t].x = fmaf(w, xv.x, acc[t].x);
            acc[t].y = fmaf(w, xv.y, acc[t].y);
            acc[t].z = fmaf(w, xv.z, acc[t].z);
            acc[t].w = fmaf(w, xv.w, acc[t].w);
        }
    }
    const float invs = 0.9999950000374997f;
    float bsc = bng[d] * invs, bof = bnb[d];
    float* orow = Out + ((size_t)b * NC + d) * NDM + j0 + jb;
    #pragma unroll
    for (int t = 0; t < 8; t++) {
        float4 xv = *(float4*)&xs[d][jb + t * 4];
        float4 o;
        o.x = (acc[t].x + xv.x) * bsc + bof;
        o.y = (acc[t].y + xv.y) * bsc + bof;
        o.z = (acc[t].z + xv.z) * bsc + bof;
        o.w = (acc[t].w + xv.w) * bsc + bof;
        *(float4*)(orow + t * 4) = o;
    }
}

// -------------------------------------------------------------------------
// 5) auto-attn shift scores + softmax + weighted shift sum.
// score_s = (u . roll_s(x)) * DM^-0.5 ; xw = sum_s w_s roll_s(x).
// one block per row, 128 threads.
__global__ void autoshift_kernel(const float* __restrict__ X, const float* __restrict__ U,
                                 float* __restrict__ XW) {
    __shared__ float xr[NDM];
    __shared__ float red[8][4];
    int row = blockIdx.x, tid = threadIdx.x;
    const float4 xv = ((const float4*)(X + (size_t)row * NDM))[tid];
    ((float4*)xr)[tid] = xv;
    const float4 uv = ((const float4*)(U + (size_t)row * NDM))[tid];
    __syncthreads();

    float sc[8];
    #pragma unroll
    for (int s = 0; s < 8; s++) {
        float4 x4 = ((float4*)xr)[(tid + 16 * s) & 127];
        sc[s] = uv.x * x4.x + uv.y * x4.y + uv.z * x4.z + uv.w * x4.w;
    }
    int lane = tid & 31, wid = tid >> 5;
    #pragma unroll
    for (int s = 0; s < 8; s++) {
        float v = sc[s];
        #pragma unroll
        for (int o = 16; o; o >>= 1) v += __shfl_xor_sync(0xffffffffu, v, o);
        if (!lane) red[s][wid] = v;
    }
    __syncthreads();
    const float rsq = 0.04419417382415922f;    // DM^-0.5
    float lg[8], mx = -1e30f;
    #pragma unroll
    for (int s = 0; s < 8; s++) {
        lg[s] = (red[s][0] + red[s][1] + red[s][2] + red[s][3]) * rsq;
        mx = fmaxf(mx, lg[s]);
    }
    float w[8], sum = 0.f;
    #pragma unroll
    for (int s = 0; s < 8; s++) { w[s] = __expf(lg[s] - mx); sum += w[s]; }
    float rs = 1.f / sum;
    float4 o = make_float4(0.f, 0.f, 0.f, 0.f);
    #pragma unroll
    for (int s = 0; s < 8; s++) {
        float4 x4 = ((float4*)xr)[(tid + 16 * s) & 127];
        float ws = w[s] * rs;
        o.x = fmaf(ws, x4.x, o.x); o.y = fmaf(ws, x4.y, o.y);
        o.z = fmaf(ws, x4.z, o.z); o.w = fmaf(ws, x4.w, o.w);
    }
    ((float4*)(XW + (size_t)row * NDM))[tid] = o;
}

// -------------------------------------------------------------------------
// 6) LayerNorm over last axis (512). one block per row, 128 threads.
__global__ void layernorm_kernel(const float* __restrict__ In, const float* __restrict__ g,
                                 const float* __restrict__ bb, float* __restrict__ Out) {
    int row = blockIdx.x, tid = threadIdx.x;
    const float4 v = ((const float4*)(In + (size_t)row * NDM))[tid];
    float s  = v.x + v.y + v.z + v.w;
    float s2 = v.x * v.x + v.y * v.y + v.z * v.z + v.w * v.w;
    #pragma unroll
    for (int o = 16; o; o >>= 1) {
        s  += __shfl_xor_sync(0xffffffffu, s, o);
        s2 += __shfl_xor_sync(0xffffffffu, s2, o);
    }
    __shared__ float ws[4], ws2[4];
    int lane = tid & 31, wid = tid >> 5;
    if (!lane) { ws[wid] = s; ws2[wid] = s2; }
    __syncthreads();
    s  = ws[0] + ws[1] + ws[2] + ws[3];
    s2 = ws2[0] + ws2[1] + ws2[2] + ws2[3];
    float mean = s * (1.f / NDM);
    float var  = s2 * (1.f / NDM) - mean * mean;
    float inv  = rsqrtf(var + 1e-5f);
    float4 gv = ((const float4*)g)[tid], bv = ((const float4*)bb)[tid];
    float4 o;
    o.x = (v.x - mean) * inv * gv.x + bv.x;
    o.y = (v.y - mean) * inv * gv.y + bv.y;
    o.z = (v.z - mean) * inv * gv.z + bv.z;
    o.w = (v.w - mean) * inv * gv.w + bv.w;
    ((float4*)(Out + (size_t)row * NDM))[tid] = o;
}

// -------------------------------------------------------------------------
extern "C" void kernel_launch(void* const* d_in, const int* in_sizes, int n_in,
                              void* d_out, int out_size) {
    (void)in_sizes; (void)n_in; (void)out_size;
    const float* inp     = (const float*)d_in[0];
    const float* ld_w    = (const float*)d_in[1];
    const float* ld_b    = (const float*)d_in[2];
    const float* emb_W   = (const float*)d_in[3];
    const float* emb_b   = (const float*)d_in[4];
    const float* W_pos   = (const float*)d_in[5];
    const float* vc_bn_g = (const float*)d_in[6];
    const float* vc_bn_b = (const float*)d_in[7];
    const float* vc_ln_g = (const float*)d_in[8];
    const float* vc_ln_b = (const float*)d_in[9];
    const float* vc_W1   = (const float*)d_in[10];
    const float* vc_b1   = (const float*)d_in[11];
    const float* vc_W2   = (const float*)d_in[12];
    const float* vc_b2   = (const float*)d_in[13];
    const float* aa_Wq   = (const float*)d_in[14];
    const float* aa_bq   = (const float*)d_in[15];
    const float* aa_Wk   = (const float*)d_in[16];
    // d_in[17] = aa_bk: provably cancels in the shift-softmax (constant logit offset)
    const float* aa_Wv   = (const float*)d_in[18];
    const float* aa_bv   = (const float*)d_in[19];
    const float* aa_Wo   = (const float*)d_in[20];
    const float* aa_bo   = (const float*)d_in[21];
    const float* aa_bn_g = (const float*)d_in[22];
    const float* aa_bn_b = (const float*)d_in[23];
    const float* aa_ln_g = (const float*)d_in[24];
    const float* aa_ln_b = (const float*)d_in[25];
    const float* aa_W1   = (const float*)d_in[26];
    const float* aa_b1   = (const float*)d_in[27];
    const float* aa_W2   = (const float*)d_in[28];
    const float* aa_b2   = (const float*)d_in[29];

    float *R, *X, *B1, *B2, *B3, *S;
    cudaGetSymbolAddress((void**)&R,  g_R);
    cudaGetSymbolAddress((void**)&X,  g_X);
    cudaGetSymbolAddress((void**)&B1, g_B1);
    cudaGetSymbolAddress((void**)&B2, g_B2);
    cudaGetSymbolAddress((void**)&B3, g_B3);
    cudaGetSymbolAddress((void**)&S,  g_S);
    float* OUT = (float*)d_out;

    dim3 gN512(NDM / GBN,  NM / GBM);   // (8,16)
    dim3 gN1024(NH / GBN,  NM / GBM);   // (16,16)

    // trend conv + residual (transposed to (B,C,T))
    conv_residual_kernel<<<dim3(NB, NT / 64, NC / 32), 256>>>(inp, ld_w, ld_b, R);
    // embedding: X = R @ emb_W.T + emb_b + W_pos
    gemm_kernel<LAY_NT, EPI_BIAS_WPOS><<<gN512, 128>>>(R, emb_W, emb_b, W_pos,
                                                       nullptr, nullptr, X, NM, NDM, NT);

    for (int l = 0; l < NL; ++l) {
        const size_t SS = (size_t)NDM * NDM, SH = (size_t)NH * NDM;
        // ---- VarCor block ----
        rowsum_kernel<<<NM / 8, 256>>>(X, S);
        varcor_kernel<<<dim3(NB, NDM / 64), 256>>>(X, S, vc_bn_g + l * NC, vc_bn_b + l * NC, B2);
        gemm_kernel<LAY_NT, EPI_BIAS_GELU><<<gN1024, 128>>>(B2, vc_W1 + l * SH, vc_b1 + l * NH,
                                                            nullptr, nullptr, nullptr, B1, NM, NH, NDM);
        gemm_kernel<LAY_NT, EPI_BIAS_RES><<<gN512, 128>>>(B1, vc_W2 + l * SH, vc_b2 + l * NDM,
                                                          B2, nullptr, nullptr, B3, NM, NDM, NH);
        layernorm_kernel<<<NM, 128>>>(B3, vc_ln_g + l * NDM, vc_ln_b + l * NDM, X);

        // ---- Auto-attention block ----
        gemm_kernel<LAY_NT, EPI_BIAS><<<gN512, 128>>>(X, aa_Wq + l * SS, aa_bq + l * NDM,
                                                      nullptr, nullptr, nullptr, B2, NM, NDM, NDM);
        gemm_kernel<LAY_NN, EPI_NONE><<<gN512, 128>>>(B2, aa_Wk + l * SS, nullptr,
                                                      nullptr, nullptr, nullptr, B3, NM, NDM, NDM);
        autoshift_kernel<<<NM, 128>>>(X, B3, B2);
        gemm_kernel<LAY_NT, EPI_BIAS><<<gN512, 128>>>(B2, aa_Wv + l * SS, aa_bv + l * NDM,
                                                      nullptr, nullptr, nullptr, B3, NM, NDM, NDM);
        gemm_kernel<LAY_NT, EPI_BIAS_RES_BN><<<gN512, 128>>>(B3, aa_Wo + l * SS, aa_bo + l * NDM,
                                                             X, aa_bn_g + l * NC, aa_bn_b + l * NC,
                                                             B2, NM, NDM, NDM);
        gemm_kernel<LAY_NT, EPI_BIAS_GELU><<<gN1024, 128>>>(B2, aa_W1 + l * SH, aa_b1 + l * NH,
                                                            nullptr, nullptr, nullptr, B1, NM, NH, NDM);
        gemm_kernel<LAY_NT, EPI_BIAS_RES><<<gN512, 128>>>(B1, aa_W2 + l * SH, aa_b2 + l * NDM,
                                                          B2, nullptr, nullptr, B3, NM, NDM, NH);
        layernorm_kernel<<<NM, 128>>>(B3, aa_ln_g + l * NDM, aa_ln_b + l * NDM,
                                      (l == NL - 1) ? OUT : X);
    }
}

// round 3
// speedup vs baseline: 2.1835x; 2.1835x over previous
#include <cuda_runtime.h>
#include <math.h>
#include <stdint.h>

// Problem constants
#define NB   16
#define NT   512
#define NC   128
#define NDM  512
#define NL   3
#define NKS  25
#define NM   (NB*NC)       // 2048 rows
#define NH   (2*NDM)       // 1024 FFN hidden

// Scratch (device globals: no allocation allowed)
__device__ float g_R  [NM*NT];
__device__ float g_X  [NM*NDM];
__device__ float g_B1 [NM*NH];
__device__ float g_B2 [NM*NDM];
__device__ float g_B3 [NM*NDM];
__device__ float g_S  [NM];
__device__ float g_WQK[NL*NDM*NDM];
__device__ float g_CV [NL*NDM];

// ===========================================================================
// tf32 warp-MMA GEMM (family-portable mma.sync; NO tcgen05 on this target)
// C[m,n] = sum_k A[m,k] * W[n,k] + epilogue.  BM=128, BN=64, BK=32.
// 256 threads = 8 warps in 4(M) x 2(N); warp tile 32x32 via m16n8k8 tf32.
// ===========================================================================
enum { EPI_NONE = 0, EPI_BIAS, EPI_BIAS_WPOS, EPI_BIAS_GELU, EPI_BIAS_RES, EPI_BIAS_RES_BN };

#define BM 128
#define BN 64
#define BK 32
#define ROWW 36                      // padded row stride (words)
#define A_STG (BM*ROWW)              // 4608 words per stage
#define B_STG (BN*ROWW)              // 2304 words per stage

__device__ __forceinline__ float to_tf32(float x) {
    uint32_t u;
    asm("cvt.rna.tf32.f32 %0, %1;" : "=r"(u) : "f"(x));
    return __uint_as_float(u);
}
__device__ __forceinline__ void mma8(float (&d)[4], const uint32_t (&a)[4], const uint32_t (&b)[2]) {
    asm volatile("mma.sync.aligned.m16n8k8.row.col.f32.tf32.tf32.f32 "
                 "{%0,%1,%2,%3}, {%4,%5,%6,%7}, {%8,%9}, {%0,%1,%2,%3};"
                 : "+f"(d[0]), "+f"(d[1]), "+f"(d[2]), "+f"(d[3])
                 : "r"(a[0]), "r"(a[1]), "r"(a[2]), "r"(a[3]), "r"(b[0]), "r"(b[1]));
}

template<int EPI>
__global__ __launch_bounds__(256)
void mma_gemm(const float* __restrict__ A, const float* __restrict__ W,
              const float* __restrict__ bias, const float* __restrict__ extra,
              const float* __restrict__ bng, const float* __restrict__ bnb,
              float* __restrict__ C, int M, int N, int K) {
    extern __shared__ float sm[];
    float* AsB = sm;                 // [2][BM][ROWW]
    float* BsB = sm + 2 * A_STG;     // [2][BN][ROWW]

    int tid = threadIdx.x, wid = tid >> 5, lane = tid & 31;
    int g = lane >> 2, tg = lane & 3;
    int wm = wid & 3, wn = wid >> 2;
    int m0 = blockIdx.y * BM, n0 = blockIdx.x * BN;

    float c[2][4][4];
    #pragma unroll
    for (int i = 0; i < 2; i++)
        #pragma unroll
        for (int j = 0; j < 4; j++)
            #pragma unroll
            for (int q = 0; q < 4; q++) c[i][j][q] = 0.f;

    float4 ra[4], rb[2];
    const int KC = K / BK;

    // ---- LDG chunk 0 ----
    {
        const float* ap = A + (size_t)m0 * K;
        #pragma unroll
        for (int i = 0; i < 4; i++) {
            int f = tid + i * 256;
            ra[i] = *(const float4*)(ap + (size_t)(f >> 3) * K + (f & 7) * 4);
        }
        const float* bp = W + (size_t)n0 * K;
        #pragma unroll
        for (int i = 0; i < 2; i++) {
            int f = tid + i * 256;
            rb[i] = *(const float4*)(bp + (size_t)(f >> 3) * K + (f & 7) * 4);
        }
    }

    for (int kc = 0; kc < KC; kc++) {
        // ---- STS (rna-rounded) ----
        {
            float* as = AsB + (kc & 1) * A_STG;
            #pragma unroll
            for (int i = 0; i < 4; i++) {
                int f = tid + i * 256;
                float4 v = ra[i];
                float4 w4 = make_float4(to_tf32(v.x), to_tf32(v.y), to_tf32(v.z), to_tf32(v.w));
                *(float4*)(as + (f >> 3) * ROWW + (f & 7) * 4) = w4;
            }
            float* bs = BsB + (kc & 1) * B_STG;
            #pragma unroll
            for (int i = 0; i < 2; i++) {
                int f = tid + i * 256;
                float4 v = rb[i];
                float4 w4 = make_float4(to_tf32(v.x), to_tf32(v.y), to_tf32(v.z), to_tf32(v.w));
                *(float4*)(bs + (f >> 3) * ROWW + (f & 7) * 4) = w4;
            }
        }
        __syncthreads();

        // ---- prefetch next chunk ----
        if (kc + 1 < KC) {
            const float* ap = A + (size_t)m0 * K + (kc + 1) * BK;
            #pragma unroll
            for (int i = 0; i < 4; i++) {
                int f = tid + i * 256;
                ra[i] = *(const float4*)(ap + (size_t)(f >> 3) * K + (f & 7) * 4);
            }
            const float* bp = W + (size_t)n0 * K + (kc + 1) * BK;
            #pragma unroll
            for (int i = 0; i < 2; i++) {
                int f = tid + i * 256;
                rb[i] = *(const float4*)(bp + (size_t)(f >> 3) * K + (f & 7) * 4);
            }
        }

        // ---- compute chunk ----
        {
            const float* as = AsB + (kc & 1) * A_STG;
            const float* bs = BsB + (kc & 1) * B_STG;
            #pragma unroll
            for (int ks = 0; ks < 4; ks++) {
                int kb = ks * 8;
                uint32_t af[2][4], bf[4][2];
                #pragma unroll
                for (int mi = 0; mi < 2; mi++) {
                    const float* base = as + (wm * 32 + mi * 16 + g) * ROWW + kb;
                    af[mi][0] = __float_as_uint(base[tg]);
                    af[mi][1] = __float_as_uint(base[8 * ROWW + tg]);
                    af[mi][2] = __float_as_uint(base[tg + 4]);
                    af[mi][3] = __float_as_uint(base[8 * ROWW + tg + 4]);
                }
                #pragma unroll
                for (int nj = 0; nj < 4; nj++) {
                    const float* base = bs + (wn * 32 + nj * 8 + g) * ROWW + kb;
                    bf[nj][0] = __float_as_uint(base[tg]);
                    bf[nj][1] = __float_as_uint(base[tg + 4]);
                }
                #pragma unroll
                for (int mi = 0; mi < 2; mi++)
                    #pragma unroll
                    for (int nj = 0; nj < 4; nj++) mma8(c[mi][nj], af[mi], bf[nj]);
            }
        }
        __syncthreads();
    }

    // ---- epilogue ----
    const float invs = 0.9999950000374997f;   // 1/sqrt(1+1e-5) eval-mode BN
    int mBase = m0 + wm * 32, nBase = n0 + wn * 32;
    #pragma unroll
    for (int mi = 0; mi < 2; mi++) {
        #pragma unroll
        for (int half = 0; half < 2; half++) {
            int m = mBase + mi * 16 + g + half * 8;
            float bsc = 1.f, bof = 0.f;
            if (EPI == EPI_BIAS_RES_BN) { bsc = bng[m & (NC - 1)] * invs; bof = bnb[m & (NC - 1)]; }
            #pragma unroll
            for (int nj = 0; nj < 4; nj++) {
                int n = nBase + nj * 8 + tg * 2;
                float x0 = c[mi][nj][half * 2 + 0];
                float x1 = c[mi][nj][half * 2 + 1];
                if (EPI != EPI_NONE) { x0 += bias[n]; x1 += bias[n + 1]; }
                if (EPI == EPI_BIAS_WPOS) {
                    const float* e = extra + (size_t)(m & (NC - 1)) * N + n;
                    x0 += e[0]; x1 += e[1];
                }
                if (EPI == EPI_BIAS_RES || EPI == EPI_BIAS_RES_BN) {
                    const float* e = extra + (size_t)m * N + n;
                    x0 += e[0]; x1 += e[1];
                }
                if (EPI == EPI_BIAS_GELU) {
                    x0 = 0.5f * x0 * (1.f + erff(x0 * 0.7071067811865475f));
                    x1 = 0.5f * x1 * (1.f + erff(x1 * 0.7071067811865475f));
                }
                if (EPI == EPI_BIAS_RES_BN) { x0 = x0 * bsc + bof; x1 = x1 * bsc + bof; }
                *(float2*)(C + (size_t)m * N + n) = make_float2(x0, x1);
            }
        }
    }
}

// ===========================================================================
// Auto-attn precompute (x-independent):
// Bop[n,k] = sum_j Wk[j,n]*Wq[j,k]  ;  cv[n] = sum_j bq[j]*Wk[j,n]
// ===========================================================================
__global__ void wqk_kernel(const float* __restrict__ Wq, const float* __restrict__ Wk,
                           float* __restrict__ Bop) {
    __shared__ float sk[16][68], sq[16][68];
    int l = blockIdx.z;
    const float* wq = Wq + (size_t)l * NDM * NDM;
    const float* wk = Wk + (size_t)l * NDM * NDM;
    float* bo = Bop + (size_t)l * NDM * NDM;
    int n0 = blockIdx.x * 64, k0 = blockIdx.y * 64;
    int tid = threadIdx.x, tx = tid & 15, ty = tid >> 4;
    float acc[4][4] = {};
    for (int j0 = 0; j0 < NDM; j0 += 16) {
        int jr = tid >> 4, qc = (tid & 15) * 4;
        *(float4*)&sk[jr][qc] = *(const float4*)(wk + (size_t)(j0 + jr) * NDM + n0 + qc);
        *(float4*)&sq[jr][qc] = *(const float4*)(wq + (size_t)(j0 + jr) * NDM + k0 + qc);
        __syncthreads();
        #pragma unroll
        for (int jj = 0; jj < 16; jj++) {
            float a[4], b[4];
            #pragma unroll
            for (int i = 0; i < 4; i++) a[i] = sk[jj][ty * 4 + i];
            #pragma unroll
            for (int j = 0; j < 4; j++) b[j] = sq[jj][tx * 4 + j];
            #pragma unroll
            for (int i = 0; i < 4; i++)
                #pragma unroll
                for (int j = 0; j < 4; j++) acc[i][j] = fmaf(a[i], b[j], acc[i][j]);
        }
        __syncthreads();
    }
    #pragma unroll
    for (int i = 0; i < 4; i++) {
        float4 v = make_float4(acc[i][0], acc[i][1], acc[i][2], acc[i][3]);
        *(float4*)(bo + (size_t)(n0 + ty * 4 + i) * NDM + k0 + tx * 4) = v;
    }
}
__global__ void bqk_kernel(const float* __restrict__ bq, const float* __restrict__ Wk,
                           float* __restrict__ cv) {
    int l = blockIdx.y;
    const float* b  = bq + l * NDM;
    const float* wk = Wk + (size_t)l * NDM * NDM;
    int n = blockIdx.x * 128 + threadIdx.x;
    float s = 0.f;
    for (int j = 0; j < NDM; j++) s = fmaf(b[j], wk[(size_t)j * NDM + n], s);
    cv[l * NDM + n] = s;
}

// ===========================================================================
// Elementwise kernels (unchanged from R1 passing version)
// ===========================================================================
__global__ void conv_residual_kernel(const float* __restrict__ inp,
                                     const float* __restrict__ w,
                                     const float* __restrict__ ldb,
                                     float* __restrict__ R) {
    __shared__ float s[88][33];
    __shared__ float wk[NKS];
    int b = blockIdx.x, t0 = blockIdx.y * 64, c0 = blockIdx.z * 32;
    int tid = threadIdx.x;
    if (tid < NKS) wk[tid] = w[tid];
    for (int idx = tid; idx < 88 * 32; idx += 256) {
        int r = idx >> 5, c = idx & 31;
        int tg = t0 + r - 12;
        tg = min(max(tg, 0), NT - 1);
        s[r][c] = inp[((size_t)b * NT + tg) * NC + c0 + c];
    }
    __syncthreads();
    float lb = ldb[0];
    int lane = tid & 31, wy = tid >> 5;
    for (int half = 0; half < 2; ++half) {
        int ti = half * 32 + lane;
        for (int cg = 0; cg < 4; ++cg) {
            int ci = cg * 8 + wy;
            float acc = 0.f;
            #pragma unroll
            for (int k = 0; k < NKS; ++k) acc = fmaf(wk[k], s[ti + k][ci], acc);
            float v = s[ti + 12][ci] - (acc + lb);
            R[((size_t)b * NC + c0 + ci) * NT + t0 + ti] = v;
        }
    }
}

__global__ void rowsum_kernel(const float* __restrict__ X, float* __restrict__ S) {
    int row = blockIdx.x * 8 + (threadIdx.x >> 5);
    int lane = threadIdx.x & 31;
    const float* xr = X + (size_t)row * NDM;
    float s = 0.f;
    for (int i = lane; i < NDM; i += 32) s += xr[i];
    #pragma unroll
    for (int o = 16; o; o >>= 1) s += __shfl_xor_sync(0xffffffffu, s, o);
    if (!lane) S[row] = s;
}

__global__ void varcor_kernel(const float* __restrict__ X, const float* __restrict__ S,
                              const float* __restrict__ bng, const float* __restrict__ bnb,
                              float* __restrict__ Out) {
    __shared__ float xs[NC][64];
    __shared__ float ss[NC];
    int b = blockIdx.x, j0 = blockIdx.y * 64;
    int tid = threadIdx.x;
    if (tid < NC) ss[tid] = S[b * NC + tid];
    const float* xb = X + (size_t)b * NC * NDM;
    for (int f = tid; f < NC * 16; f += 256) {
        int e = f >> 4, q = f & 15;
        *(float4*)&xs[e][q * 4] = ((const float4*)(xb + (size_t)e * NDM + j0))[q];
    }
    __syncthreads();

    int d = tid >> 1, half = tid & 1;
    const float VS = 8.6316746e-05f;            // 1/(512*sqrt(512))
    float sd = ss[d];
    float mx = -1e30f;
    for (int e = 0; e < NC; e++) mx = fmaxf(mx, sd * ss[e]);
    float sum = 0.f;
    for (int e = 0; e < NC; e++) sum += __expf((sd * ss[e] - mx) * VS);
    float rs = 1.f / sum;

    float4 acc[8];
    #pragma unroll
    for (int t = 0; t < 8; t++) acc[t] = make_float4(0.f, 0.f, 0.f, 0.f);
    int jb = half * 32;
    for (int e = 0; e < NC; e++) {
        float w = __expf((sd * ss[e] - mx) * VS) * rs;
        #pragma unroll
        for (int t = 0; t < 8; t++) {
            float4 xv = *(float4*)&xs[e][jb + t * 4];
            acc[t].x = fmaf(w, xv.x, acc[t].x);
            acc[t].y = fmaf(w, xv.y, acc[t].y);
            acc[t].z = fmaf(w, xv.z, acc[t].z);
            acc[t].w = fmaf(w, xv.w, acc[t].w);
        }
    }
    const float invs = 0.9999950000374997f;
    float bsc = bng[d] * invs, bof = bnb[d];
    float* orow = Out + ((size_t)b * NC + d) * NDM + j0 + jb;
    #pragma unroll
    for (int t = 0; t < 8; t++) {
        float4 xv = *(float4*)&xs[d][jb + t * 4];
        float4 o;
        o.x = (acc[t].x + xv.x) * bsc + bof;
        o.y = (acc[t].y + xv.y) * bsc + bof;
        o.z = (acc[t].z + xv.z) * bsc + bof;
        o.w = (acc[t].w + xv.w) * bsc + bof;
        *(float4*)(orow + t * 4) = o;
    }
}

__global__ void autoshift_kernel(const float* __restrict__ X, const float* __restrict__ U,
                                 float* __restrict__ XW) {
    __shared__ float xr[NDM];
    __shared__ float red[8][4];
    int row = blockIdx.x, tid = threadIdx.x;
    const float4 xv = ((const float4*)(X + (size_t)row * NDM))[tid];
    ((float4*)xr)[tid] = xv;
    const float4 uv = ((const float4*)(U + (size_t)row * NDM))[tid];
    __syncthreads();

    float sc[8];
    #pragma unroll
    for (int s = 0; s < 8; s++) {
        float4 x4 = ((float4*)xr)[(tid + 16 * s) & 127];
        sc[s] = uv.x * x4.x + uv.y * x4.y + uv.z * x4.z + uv.w * x4.w;
    }
    int lane = tid & 31, wid = tid >> 5;
    #pragma unroll
    for (int s = 0; s < 8; s++) {
        float v = sc[s];
        #pragma unroll
        for (int o = 16; o; o >>= 1) v += __shfl_xor_sync(0xffffffffu, v, o);
        if (!lane) red[s][wid] = v;
    }
    __syncthreads();
    const float rsq = 0.04419417382415922f;    // DM^-0.5
    float lg[8], mx = -1e30f;
    #pragma unroll
    for (int s = 0; s < 8; s++) {
        lg[s] = (red[s][0] + red[s][1] + red[s][2] + red[s][3]) * rsq;
        mx = fmaxf(mx, lg[s]);
    }
    float w[8], sum = 0.f;
    #pragma unroll
    for (int s = 0; s < 8; s++) { w[s] = __expf(lg[s] - mx); sum += w[s]; }
    float rs = 1.f / sum;
    float4 o = make_float4(0.f, 0.f, 0.f, 0.f);
    #pragma unroll
    for (int s = 0; s < 8; s++) {
        float4 x4 = ((float4*)xr)[(tid + 16 * s) & 127];
        float ws = w[s] * rs;
        o.x = fmaf(ws, x4.x, o.x); o.y = fmaf(ws, x4.y, o.y);
        o.z = fmaf(ws, x4.z, o.z); o.w = fmaf(ws, x4.w, o.w);
    }
    ((float4*)(XW + (size_t)row * NDM))[tid] = o;
}

__global__ void layernorm_kernel(const float* __restrict__ In, const float* __restrict__ g,
                                 const float* __restrict__ bb, float* __restrict__ Out) {
    int row = blockIdx.x, tid = threadIdx.x;
    const float4 v = ((const float4*)(In + (size_t)row * NDM))[tid];
    float s  = v.x + v.y + v.z + v.w;
    float s2 = v.x * v.x + v.y * v.y + v.z * v.z + v.w * v.w;
    #pragma unroll
    for (int o = 16; o; o >>= 1) {
        s  += __shfl_xor_sync(0xffffffffu, s, o);
        s2 += __shfl_xor_sync(0xffffffffu, s2, o);
    }
    __shared__ float ws[4], ws2[4];
    int lane = tid & 31, wid = tid >> 5;
    if (!lane) { ws[wid] = s; ws2[wid] = s2; }
    __syncthreads();
    s  = ws[0] + ws[1] + ws[2] + ws[3];
    s2 = ws2[0] + ws2[1] + ws2[2] + ws2[3];
    float mean = s * (1.f / NDM);
    float var  = s2 * (1.f / NDM) - mean * mean;
    float inv  = rsqrtf(var + 1e-5f);
    float4 gv = ((const float4*)g)[tid], bv = ((const float4*)bb)[tid];
    float4 o;
    o.x = (v.x - mean) * inv * gv.x + bv.x;
    o.y = (v.y - mean) * inv * gv.y + bv.y;
    o.z = (v.z - mean) * inv * gv.z + bv.z;
    o.w = (v.w - mean) * inv * gv.w + bv.w;
    ((float4*)(Out + (size_t)row * NDM))[tid] = o;
}

// ===========================================================================
extern "C" void kernel_launch(void* const* d_in, const int* in_sizes, int n_in,
                              void* d_out, int out_size) {
    (void)in_sizes; (void)n_in; (void)out_size;
    const float* inp     = (const float*)d_in[0];
    const float* ld_w    = (const float*)d_in[1];
    const float* ld_b    = (const float*)d_in[2];
    const float* emb_W   = (const float*)d_in[3];
    const float* emb_b   = (const float*)d_in[4];
    const float* W_pos   = (const float*)d_in[5];
    const float* vc_bn_g = (const float*)d_in[6];
    const float* vc_bn_b = (const float*)d_in[7];
    const float* vc_ln_g = (const float*)d_in[8];
    const float* vc_ln_b = (const float*)d_in[9];
    const float* vc_W1   = (const float*)d_in[10];
    const float* vc_b1   = (const float*)d_in[11];
    const float* vc_W2   = (const float*)d_in[12];
    const float* vc_b2   = (const float*)d_in[13];
    const float* aa_Wq   = (const float*)d_in[14];
    const float* aa_bq   = (const float*)d_in[15];
    const float* aa_Wk   = (const float*)d_in[16];
    // d_in[17] = aa_bk: cancels in the shift-softmax (constant logit offset)
    const float* aa_Wv   = (const float*)d_in[18];
    const float* aa_bv   = (const float*)d_in[19];
    const float* aa_Wo   = (const float*)d_in[20];
    const float* aa_bo   = (const float*)d_in[21];
    const float* aa_bn_g = (const float*)d_in[22];
    const float* aa_bn_b = (const float*)d_in[23];
    const float* aa_ln_g = (const float*)d_in[24];
    const float* aa_ln_b = (const float*)d_in[25];
    const float* aa_W1   = (const float*)d_in[26];
    const float* aa_b1   = (const float*)d_in[27];
    const float* aa_W2   = (const float*)d_in[28];
    const float* aa_b2   = (const float*)d_in[29];

    float *R, *X, *B1, *B2, *B3, *S, *WQK, *CV;
    cudaGetSymbolAddress((void**)&R,   g_R);
    cudaGetSymbolAddress((void**)&X,   g_X);
    cudaGetSymbolAddress((void**)&B1,  g_B1);
    cudaGetSymbolAddress((void**)&B2,  g_B2);
    cudaGetSymbolAddress((void**)&B3,  g_B3);
    cudaGetSymbolAddress((void**)&S,   g_S);
    cudaGetSymbolAddress((void**)&WQK, g_WQK);
    cudaGetSymbolAddress((void**)&CV,  g_CV);
    float* OUT = (float*)d_out;

    const int SMEM = 2 * (A_STG + B_STG) * 4;    // 55296 bytes
    static int smem_set = 0;
    cudaFuncSetAttribute(mma_gemm<EPI_BIAS>,        cudaFuncAttributeMaxDynamicSharedMemorySize, SMEM);
    cudaFuncSetAttribute(mma_gemm<EPI_BIAS_WPOS>,   cudaFuncAttributeMaxDynamicSharedMemorySize, SMEM);
    cudaFuncSetAttribute(mma_gemm<EPI_BIAS_GELU>,   cudaFuncAttributeMaxDynamicSharedMemorySize, SMEM);
    cudaFuncSetAttribute(mma_gemm<EPI_BIAS_RES>,    cudaFuncAttributeMaxDynamicSharedMemorySize, SMEM);
    cudaFuncSetAttribute(mma_gemm<EPI_BIAS_RES_BN>, cudaFuncAttributeMaxDynamicSharedMemorySize, SMEM);
    (void)smem_set;

    dim3 g512(NDM / BN, NM / BM);    // (8,16)  = 128 blocks
    dim3 g1024(NH / BN, NM / BM);    // (16,16) = 256 blocks

    // trend conv + residual (transposed to (B,C,T))
    conv_residual_kernel<<<dim3(NB, NT / 64, NC / 32), 256>>>(inp, ld_w, ld_b, R);
    // auto-attn precompute (x-independent, all layers)
    wqk_kernel<<<dim3(8, 8, NL), 256>>>(aa_Wq, aa_Wk, WQK);
    bqk_kernel<<<dim3(4, NL), 128>>>(aa_bq, aa_Wk, CV);
    // embedding: X = R @ emb_W.T + emb_b + W_pos
    mma_gemm<EPI_BIAS_WPOS><<<g512, 256, SMEM>>>(R, emb_W, emb_b, W_pos,
                                                 nullptr, nullptr, X, NM, NDM, NT);

    for (int l = 0; l < NL; ++l) {
        const size_t SS = (size_t)NDM * NDM, SH = (size_t)NH * NDM;
        // ---- VarCor block ----
        rowsum_kernel<<<NM / 8, 256>>>(X, S);
        varcor_kernel<<<dim3(NB, NDM / 64), 256>>>(X, S, vc_bn_g + l * NC, vc_bn_b + l * NC, B2);
        mma_gemm<EPI_BIAS_GELU><<<g1024, 256, SMEM>>>(B2, vc_W1 + l * SH, vc_b1 + l * NH,
                                                      nullptr, nullptr, nullptr, B1, NM, NH, NDM);
        mma_gemm<EPI_BIAS_RES><<<g512, 256, SMEM>>>(B1, vc_W2 + l * SH, vc_b2 + l * NDM,
                                                    B2, nullptr, nullptr, B3, NM, NDM, NH);
        layernorm_kernel<<<NM, 128>>>(B3, vc_ln_g + l * NDM, vc_ln_b + l * NDM, X);

        // ---- Auto-attention block ----
        // u = x @ (Wq^T Wk)^T-form + bq@Wk   (single fused GEMM, NT layout)
        mma_gemm<EPI_BIAS><<<g512, 256, SMEM>>>(X, WQK + l * SS, CV + l * NDM,
                                                nullptr, nullptr, nullptr, B3, NM, NDM, NDM);
        autoshift_kernel<<<NM, 128>>>(X, B3, B2);
        mma_gemm<EPI_BIAS><<<g512, 256, SMEM>>>(B2, aa_Wv + l * SS, aa_bv + l * NDM,
                                                nullptr, nullptr, nullptr, B3, NM, NDM, NDM);
        mma_gemm<EPI_BIAS_RES_BN><<<g512, 256, SMEM>>>(B3, aa_Wo + l * SS, aa_bo + l * NDM,
                                                       X, aa_bn_g + l * NC, aa_bn_b + l * NC,
                                                       B2, NM, NDM, NDM);
        mma_gemm<EPI_BIAS_GELU><<<g1024, 256, SMEM>>>(B2, aa_W1 + l * SH, aa_b1 + l * NH,
                                                      nullptr, nullptr, nullptr, B1, NM, NH, NDM);
        mma_gemm<EPI_BIAS_RES><<<g512, 256, SMEM>>>(B1, aa_W2 + l * SH, aa_b2 + l * NDM,
                                                    B2, nullptr, nullptr, B3, NM, NDM, NH);
        layernorm_kernel<<<NM, 128>>>(B3, aa_ln_g + l * NDM, aa_ln_b + l * NDM,
                                      (l == NL - 1) ? OUT : X);
    }
}